// round 5
// baseline (speedup 1.0000x reference)
#include <cuda_runtime.h>
#include <cstdint>

#define NN 100000
#define EE 1600000
#define DD 128
#define NBLK ((NN + 1023) / 1024)   // 98 scan blocks

// ---------------- static device scratch (no allocation allowed) ----------------
__device__ float g_h[NN * DD];                // layer-1 output
__device__ float g_wfrag1[16 * 16 * 32 * 2];  // W1 mma B-fragment table (64KB)
__device__ float g_wfrag2[16 * 16 * 32 * 2];  // W2 fragment table
__device__ int   g_outdeg[NN];
__device__ int   g_indeg[NN];
__device__ int   g_rowptr[NN + 1];
__device__ int   g_cursor[NN];
__device__ int   g_colidx[EE];
__device__ float g_inv[NN];
__device__ int   g_bsum[NBLK];
__device__ int   g_boff[NBLK];

__device__ __forceinline__ uint32_t f2tf32(float x) {
    uint32_t r;
    asm("cvt.rna.tf32.f32 %0, %1;" : "=r"(r) : "f"(x));
    return r;
}

#define MMA_TF32(c0, c1, c2, c3, a0, a1, a2, a3, b0, b1) \
    asm volatile("mma.sync.aligned.m16n8k8.row.col.f32.tf32.tf32.f32 " \
        "{%0,%1,%2,%3}, {%4,%5,%6,%7}, {%8,%9}, {%0,%1,%2,%3};" \
        : "+f"(c0), "+f"(c1), "+f"(c2), "+f"(c3) \
        : "r"(a0), "r"(a1), "r"(a2), "r"(a3), "r"(b0), "r"(b1))

// ---------------- build: degrees ----------------
__global__ void k_init(int N) {
    int i = blockIdx.x * blockDim.x + threadIdx.x;
    if (i < N) { g_outdeg[i] = 0; g_indeg[i] = 0; }
}

__global__ void k_deg(const int* __restrict__ src, const int* __restrict__ dst, int E) {
    int e = blockIdx.x * blockDim.x + threadIdx.x;
    if (e < E) {
        atomicAdd(&g_outdeg[src[e]], 1);
        atomicAdd(&g_indeg[dst[e]], 1);
    }
}

__global__ void k_inv(int N) {
    int i = blockIdx.x * blockDim.x + threadIdx.x;
    if (i < N) {
        int d = g_outdeg[i];
        g_inv[i] = 1.0f / (float)(d > 1 ? d : 1);
    }
}

// ---------------- build: parallel exclusive scan ----------------
__global__ void k_scan1(int N) {
    __shared__ int s_w[32];
    int tid = threadIdx.x, lane = tid & 31, wid = tid >> 5;
    int i = blockIdx.x * 1024 + tid;
    int v = (i < N) ? g_indeg[i] : 0;
    int incl = v;
#pragma unroll
    for (int off = 1; off < 32; off <<= 1) {
        int t = __shfl_up_sync(0xffffffffu, incl, off);
        if (lane >= off) incl += t;
    }
    if (lane == 31) s_w[wid] = incl;
    __syncthreads();
    if (wid == 0) {
        int s = s_w[lane];
        int si = s;
#pragma unroll
        for (int off = 1; off < 32; off <<= 1) {
            int t = __shfl_up_sync(0xffffffffu, si, off);
            if (lane >= off) si += t;
        }
        s_w[lane] = si - s;
    }
    __syncthreads();
    int excl = incl - v + s_w[wid];
    if (i < N) g_rowptr[i] = excl;
    if (tid == 1023) g_bsum[blockIdx.x] = s_w[31] + incl;
}

__global__ void k_scan2() {
    __shared__ int s[NBLK];
    int tid = threadIdx.x;
    if (tid < NBLK) s[tid] = g_bsum[tid];
    __syncthreads();
    if (tid == 0) {
        int run = 0;
        for (int b = 0; b < NBLK; b++) { int t = s[b]; s[b] = run; run += t; }
    }
    __syncthreads();
    if (tid < NBLK) g_boff[tid] = s[tid];
}

__global__ void k_scan3(int N, int E) {
    int i = blockIdx.x * blockDim.x + threadIdx.x;
    if (i < N) {
        int v = g_rowptr[i] + g_boff[i >> 10];
        g_rowptr[i] = v;
        g_cursor[i] = v;
    }
    if (i == 0) g_rowptr[N] = E;
}

__global__ void k_scatter(const int* __restrict__ src, const int* __restrict__ dst, int E) {
    int e = blockIdx.x * blockDim.x + threadIdx.x;
    if (e < E) {
        int p = atomicAdd(&g_cursor[dst[e]], 1);
        g_colidx[p] = src[e];
    }
}

// ---------------- pack W into mma B-fragment table ----------------
// frag[(ks*16 + nt)*32 + lane] = float2{ W[ks*8 + lane%4][nt*8 + lane/4],
//                                        W[ks*8 + 4 + lane%4][nt*8 + lane/4] }  (tf32)
__global__ void k_wfrag(const float* __restrict__ W, float* __restrict__ frag) {
    int idx = blockIdx.x * 256 + threadIdx.x;   // 0..8191
    if (idx >= 8192) return;
    int lane = idx & 31, nt = (idx >> 5) & 15, ks = idx >> 9;
    int k0 = ks * 8, col = nt * 8 + (lane >> 2), r = lane & 3;
    float2 o;
    o.x = __uint_as_float(f2tf32(W[(k0 + r) * DD + col]));
    o.y = __uint_as_float(f2tf32(W[(k0 + 4 + r) * DD + col]));
    ((float2*)frag)[idx] = o;
}

// ---------------- FUSED gather + tf32 mma GEMM + bias + PReLU ----------------
// CTA: 64 dst rows x 128 cols. Phase 1: each warp gathers 8 rows (segment-sum of
// normalized source features) straight into the smem A tile (tf32). Phase 2:
// 8-warp mma, warp tile 16x64, B frags from L1-resident gmem table.
#define ASTRIDE 132
__global__ __launch_bounds__(256, 2)
void k_fused(const float4* __restrict__ xin, const float* __restrict__ wfrag,
             const float* __restrict__ bias, const float* __restrict__ pa,
             float* __restrict__ out, int N) {
    __shared__ float As[64 * ASTRIDE];
    int tid = threadIdx.x;
    int lane = tid & 31, wid = tid >> 5;
    int rbase = blockIdx.x * 64;

    // ---- Phase 1: gather 8 rows per warp into As ----
#pragma unroll 1
    for (int r8 = 0; r8 < 8; r8++) {
        int r = wid * 8 + r8;
        int row = rbase + r;
        float4 acc = make_float4(0.f, 0.f, 0.f, 0.f);
        if (row < N) {
            int beg = g_rowptr[row], end = g_rowptr[row + 1];
            for (int e = beg; e < end; e++) {
                int s = g_colidx[e];
                float sc = g_inv[s];
                float4 v = xin[s * 32 + lane];
                acc.x += v.x * sc;
                acc.y += v.y * sc;
                acc.z += v.z * sc;
                acc.w += v.w * sc;
            }
        }
        float4 t;
        t.x = __uint_as_float(f2tf32(acc.x));
        t.y = __uint_as_float(f2tf32(acc.y));
        t.z = __uint_as_float(f2tf32(acc.z));
        t.w = __uint_as_float(f2tf32(acc.w));
        *(float4*)&As[r * ASTRIDE + lane * 4] = t;
    }
    __syncthreads();

    // ---- Phase 2: mma ----
    int rowgrp = wid & 3, colgrp = wid >> 2;
    float c[8][4];
#pragma unroll
    for (int nt = 0; nt < 8; nt++)
#pragma unroll
        for (int j = 0; j < 4; j++) c[nt][j] = 0.f;

    const float* Ab = As + (rowgrp * 16 + (lane >> 2)) * ASTRIDE + (lane & 3);
    const float2* wf = (const float2*)wfrag;

#pragma unroll
    for (int ks = 0; ks < 16; ks++) {
        int k0 = ks * 8;
        uint32_t a0 = __float_as_uint(Ab[k0]);
        uint32_t a1 = __float_as_uint(Ab[8 * ASTRIDE + k0]);
        uint32_t a2 = __float_as_uint(Ab[k0 + 4]);
        uint32_t a3 = __float_as_uint(Ab[8 * ASTRIDE + k0 + 4]);
        const float2* wk = wf + (ks * 16 + colgrp * 8) * 32 + lane;
#pragma unroll
        for (int nt = 0; nt < 8; nt++) {
            float2 bv = wk[nt * 32];
            MMA_TF32(c[nt][0], c[nt][1], c[nt][2], c[nt][3],
                     a0, a1, a2, a3,
                     __float_as_uint(bv.x), __float_as_uint(bv.y));
        }
    }

    // ---- Epilogue: bias + PReLU ----
    float alpha = pa[0];
    int r_lo = rbase + rowgrp * 16 + (lane >> 2);
    int r_hi = r_lo + 8;
#pragma unroll
    for (int nt = 0; nt < 8; nt++) {
        int col = colgrp * 64 + nt * 8 + (lane & 3) * 2;
        float2 bb = *(const float2*)(bias + col);
        float z0 = c[nt][0] + bb.x;
        float z1 = c[nt][1] + bb.y;
        float z2 = c[nt][2] + bb.x;
        float z3 = c[nt][3] + bb.y;
        z0 = (z0 >= 0.f) ? z0 : alpha * z0;
        z1 = (z1 >= 0.f) ? z1 : alpha * z1;
        z2 = (z2 >= 0.f) ? z2 : alpha * z2;
        z3 = (z3 >= 0.f) ? z3 : alpha * z3;
        if (r_lo < N) { float2 o = {z0, z1}; *(float2*)(out + r_lo * DD + col) = o; }
        if (r_hi < N) { float2 o = {z2, z3}; *(float2*)(out + r_hi * DD + col) = o; }
    }
}

// ---------------- launch ----------------
extern "C" void kernel_launch(void* const* d_in, const int* in_sizes, int n_in,
                              void* d_out, int out_size) {
    const float* x   = (const float*)d_in[0];
    const int*   src = (const int*)d_in[1];
    const int*   dst = (const int*)d_in[2];
    const float* W1  = (const float*)d_in[3];
    const float* b1  = (const float*)d_in[4];
    const float* W2  = (const float*)d_in[5];
    const float* b2  = (const float*)d_in[6];
    const float* pa  = (const float*)d_in[7];
    float* out = (float*)d_out;

    const int N = NN;
    const int E = EE;

    float *h, *wf1, *wf2;
    cudaGetSymbolAddress((void**)&h, g_h);
    cudaGetSymbolAddress((void**)&wf1, g_wfrag1);
    cudaGetSymbolAddress((void**)&wf2, g_wfrag2);

    // Build CSR + normalization + W fragment tables
    k_init<<<(N + 255) / 256, 256>>>(N);
    k_deg<<<(E + 255) / 256, 256>>>(src, dst, E);
    k_inv<<<(N + 255) / 256, 256>>>(N);
    k_scan1<<<NBLK, 1024>>>(N);
    k_scan2<<<1, 128>>>();
    k_scan3<<<(N + 255) / 256, 256>>>(N, E);
    k_scatter<<<(E + 255) / 256, 256>>>(src, dst, E);
    k_wfrag<<<32, 256>>>(W1, wf1);
    k_wfrag<<<32, 256>>>(W2, wf2);

    int mblocks = (N + 63) / 64;   // 1563

    // Layer 1 (fused gather+GEMM): reads x, writes h
    k_fused<<<mblocks, 256>>>((const float4*)x, wf1, b1, pa, h, N);
    // Layer 2: reads h, writes out
    k_fused<<<mblocks, 256>>>((const float4*)h, wf2, b2, pa, out, N);
}

// round 6
// speedup vs baseline: 1.0792x; 1.0792x over previous
#include <cuda_runtime.h>
#include <cstdint>

#define NN 100000
#define EE 1600000
#define DD 128
#define NBLK ((NN + 1023) / 1024)   // 98 scan blocks

// ---------------- static device scratch (no allocation allowed) ----------------
__device__ float g_agg[NN * DD];       // SpMM output / GEMM input
__device__ float g_h[NN * DD];         // layer-1 output (pre-scaled by inv)
__device__ float g_wfrag1[16 * 16 * 32 * 2];  // W1 mma B-fragment table (64KB)
__device__ float g_wfrag2[16 * 16 * 32 * 2];  // W2 fragment table
__device__ int   g_outdeg[NN];
__device__ int   g_indeg[NN];
__device__ int   g_rowptr[NN + 1];
__device__ int   g_cursor[NN];
__device__ int   g_colidx[EE];
__device__ float g_inv[NN];
__device__ int   g_bsum[NBLK];
__device__ int   g_boff[NBLK];

__device__ __forceinline__ uint32_t f2tf32(float x) {
    uint32_t r;
    asm("cvt.rna.tf32.f32 %0, %1;" : "=r"(r) : "f"(x));
    return r;
}

#define MMA_TF32(c0, c1, c2, c3, a0, a1, a2, a3, b0, b1) \
    asm volatile("mma.sync.aligned.m16n8k8.row.col.f32.tf32.tf32.f32 " \
        "{%0,%1,%2,%3}, {%4,%5,%6,%7}, {%8,%9}, {%0,%1,%2,%3};" \
        : "+f"(c0), "+f"(c1), "+f"(c2), "+f"(c3) \
        : "r"(a0), "r"(a1), "r"(a2), "r"(a3), "r"(b0), "r"(b1))

// ---------------- build: degrees ----------------
__global__ void k_init(int N) {
    int i = blockIdx.x * blockDim.x + threadIdx.x;
    if (i < N) { g_outdeg[i] = 0; g_indeg[i] = 0; }
}

__global__ void k_deg(const int* __restrict__ src, const int* __restrict__ dst, int E) {
    int e = blockIdx.x * blockDim.x + threadIdx.x;
    if (e < E) {
        atomicAdd(&g_outdeg[src[e]], 1);
        atomicAdd(&g_indeg[dst[e]], 1);
    }
}

// ---------------- build: parallel exclusive scan ----------------
__global__ void k_scan1(int N) {
    __shared__ int s_w[32];
    int tid = threadIdx.x, lane = tid & 31, wid = tid >> 5;
    int i = blockIdx.x * 1024 + tid;
    int v = (i < N) ? g_indeg[i] : 0;
    int incl = v;
#pragma unroll
    for (int off = 1; off < 32; off <<= 1) {
        int t = __shfl_up_sync(0xffffffffu, incl, off);
        if (lane >= off) incl += t;
    }
    if (lane == 31) s_w[wid] = incl;
    __syncthreads();
    if (wid == 0) {
        int s = s_w[lane];
        int si = s;
#pragma unroll
        for (int off = 1; off < 32; off <<= 1) {
            int t = __shfl_up_sync(0xffffffffu, si, off);
            if (lane >= off) si += t;
        }
        s_w[lane] = si - s;
    }
    __syncthreads();
    int excl = incl - v + s_w[wid];
    if (i < N) g_rowptr[i] = excl;
    if (tid == 1023) g_bsum[blockIdx.x] = s_w[31] + incl;
}

__global__ void k_scan2() {
    __shared__ int s[NBLK];
    int tid = threadIdx.x;
    if (tid < NBLK) s[tid] = g_bsum[tid];
    __syncthreads();
    if (tid == 0) {
        int run = 0;
        for (int b = 0; b < NBLK; b++) { int t = s[b]; s[b] = run; run += t; }
    }
    __syncthreads();
    if (tid < NBLK) g_boff[tid] = s[tid];
}

// scan3 also computes inv (merged former k_inv)
__global__ void k_scan3(int N, int E) {
    int i = blockIdx.x * blockDim.x + threadIdx.x;
    if (i < N) {
        int v = g_rowptr[i] + g_boff[i >> 10];
        g_rowptr[i] = v;
        g_cursor[i] = v;
        int d = g_outdeg[i];
        g_inv[i] = 1.0f / (float)(d > 1 ? d : 1);
    }
    if (i == 0) g_rowptr[N] = E;
}

__global__ void k_scatter(const int* __restrict__ src, const int* __restrict__ dst, int E) {
    int e = blockIdx.x * blockDim.x + threadIdx.x;
    if (e < E) {
        int p = atomicAdd(&g_cursor[dst[e]], 1);
        g_colidx[p] = src[e];
    }
}

// ---------------- pack W into mma B-fragment table ----------------
__global__ void k_wfrag(const float* __restrict__ W, float* __restrict__ frag) {
    int idx = blockIdx.x * 256 + threadIdx.x;   // 0..8191
    if (idx >= 8192) return;
    int lane = idx & 31, nt = (idx >> 5) & 15, ks = idx >> 9;
    int k0 = ks * 8, col = nt * 8 + (lane >> 2), r = lane & 3;
    float2 o;
    o.x = __uint_as_float(f2tf32(W[(k0 + r) * DD + col]));
    o.y = __uint_as_float(f2tf32(W[(k0 + 4 + r) * DD + col]));
    ((float2*)frag)[idx] = o;
}

// ---------------- SpMM gather (unroll x4, 2 accumulators) ----------------
// SCALE=true: multiply each source row by g_inv[src] (layer 1).
// SCALE=false: plain sum (layer 2; h pre-scaled in GEMM-1 epilogue).
template <bool SCALE>
__global__ void k_gather(const float4* __restrict__ xin, float4* __restrict__ out, int N) {
    int lane = threadIdx.x;
    int node = blockIdx.x * blockDim.y + threadIdx.y;
    if (node >= N) return;
    int beg = g_rowptr[node], end = g_rowptr[node + 1];
    float4 a0 = make_float4(0.f, 0.f, 0.f, 0.f);
    float4 a1 = make_float4(0.f, 0.f, 0.f, 0.f);
    int e = beg;
    for (; e + 4 <= end; e += 4) {
        int s0 = g_colidx[e + 0];
        int s1 = g_colidx[e + 1];
        int s2 = g_colidx[e + 2];
        int s3 = g_colidx[e + 3];
        float4 v0 = xin[s0 * 32 + lane];
        float4 v1 = xin[s1 * 32 + lane];
        float4 v2 = xin[s2 * 32 + lane];
        float4 v3 = xin[s3 * 32 + lane];
        if (SCALE) {
            float c0 = g_inv[s0], c1 = g_inv[s1], c2 = g_inv[s2], c3 = g_inv[s3];
            a0.x += v0.x * c0; a0.y += v0.y * c0; a0.z += v0.z * c0; a0.w += v0.w * c0;
            a1.x += v1.x * c1; a1.y += v1.y * c1; a1.z += v1.z * c1; a1.w += v1.w * c1;
            a0.x += v2.x * c2; a0.y += v2.y * c2; a0.z += v2.z * c2; a0.w += v2.w * c2;
            a1.x += v3.x * c3; a1.y += v3.y * c3; a1.z += v3.z * c3; a1.w += v3.w * c3;
        } else {
            a0.x += v0.x; a0.y += v0.y; a0.z += v0.z; a0.w += v0.w;
            a1.x += v1.x; a1.y += v1.y; a1.z += v1.z; a1.w += v1.w;
            a0.x += v2.x; a0.y += v2.y; a0.z += v2.z; a0.w += v2.w;
            a1.x += v3.x; a1.y += v3.y; a1.z += v3.z; a1.w += v3.w;
        }
    }
    for (; e < end; e++) {
        int s = g_colidx[e];
        float4 v = xin[s * 32 + lane];
        float c = SCALE ? g_inv[s] : 1.0f;
        a0.x += v.x * c; a0.y += v.y * c; a0.z += v.z * c; a0.w += v.w * c;
    }
    a0.x += a1.x; a0.y += a1.y; a0.z += a1.z; a0.w += a1.w;
    out[node * 32 + lane] = a0;
}

// ---------------- tf32 mma.sync GEMM + bias + PReLU (+ optional inv scale) ----------------
// CTA: 64 rows x 128 cols, 8 warps, warp tile 16x64.
// OUTSCALE=true: multiply output row by g_inv[row] (prepares layer-2 gather input).
#define ASTRIDE 132
template <bool OUTSCALE>
__global__ __launch_bounds__(256, 2)
void k_gemm_mma(const float* __restrict__ A, const float* __restrict__ wfrag,
                const float* __restrict__ bias, const float* __restrict__ pa,
                float* __restrict__ out, int N) {
    __shared__ float As[64 * ASTRIDE];
    int tid = threadIdx.x;
    int lane = tid & 31, wid = tid >> 5;
    int rowgrp = wid & 3, colgrp = wid >> 2;
    int rbase = blockIdx.x * 64;

    const float4* A4 = (const float4*)A;
    for (int i = tid; i < 64 * 32; i += 256) {
        int r = i >> 5, c4 = i & 31;
        int row = rbase + r;
        if (row >= N) row = N - 1;   // clamp; extra rows never stored
        float4 v = A4[row * 32 + c4];
        float4 t;
        t.x = __uint_as_float(f2tf32(v.x));
        t.y = __uint_as_float(f2tf32(v.y));
        t.z = __uint_as_float(f2tf32(v.z));
        t.w = __uint_as_float(f2tf32(v.w));
        *(float4*)&As[r * ASTRIDE + c4 * 4] = t;
    }
    __syncthreads();

    float c[8][4];
#pragma unroll
    for (int nt = 0; nt < 8; nt++)
#pragma unroll
        for (int j = 0; j < 4; j++) c[nt][j] = 0.f;

    const float* Ab = As + (rowgrp * 16 + (lane >> 2)) * ASTRIDE + (lane & 3);
    const float2* wf = (const float2*)wfrag;

#pragma unroll
    for (int ks = 0; ks < 16; ks++) {
        int k0 = ks * 8;
        uint32_t a0 = __float_as_uint(Ab[k0]);
        uint32_t a1 = __float_as_uint(Ab[8 * ASTRIDE + k0]);
        uint32_t a2 = __float_as_uint(Ab[k0 + 4]);
        uint32_t a3 = __float_as_uint(Ab[8 * ASTRIDE + k0 + 4]);
        const float2* wk = wf + (ks * 16 + colgrp * 8) * 32 + lane;
#pragma unroll
        for (int nt = 0; nt < 8; nt++) {
            float2 bv = wk[nt * 32];
            MMA_TF32(c[nt][0], c[nt][1], c[nt][2], c[nt][3],
                     a0, a1, a2, a3,
                     __float_as_uint(bv.x), __float_as_uint(bv.y));
        }
    }

    float alpha = pa[0];
    int r_lo = rbase + rowgrp * 16 + (lane >> 2);
    int r_hi = r_lo + 8;
    float s_lo = 1.f, s_hi = 1.f;
    if (OUTSCALE) {
        if (r_lo < N) s_lo = g_inv[r_lo];
        if (r_hi < N) s_hi = g_inv[r_hi];
    }
#pragma unroll
    for (int nt = 0; nt < 8; nt++) {
        int col = colgrp * 64 + nt * 8 + (lane & 3) * 2;
        float2 bb = *(const float2*)(bias + col);
        float z0 = c[nt][0] + bb.x;
        float z1 = c[nt][1] + bb.y;
        float z2 = c[nt][2] + bb.x;
        float z3 = c[nt][3] + bb.y;
        z0 = (z0 >= 0.f) ? z0 : alpha * z0;
        z1 = (z1 >= 0.f) ? z1 : alpha * z1;
        z2 = (z2 >= 0.f) ? z2 : alpha * z2;
        z3 = (z3 >= 0.f) ? z3 : alpha * z3;
        if (OUTSCALE) { z0 *= s_lo; z1 *= s_lo; z2 *= s_hi; z3 *= s_hi; }
        if (r_lo < N) { float2 o = {z0, z1}; *(float2*)(out + r_lo * DD + col) = o; }
        if (r_hi < N) { float2 o = {z2, z3}; *(float2*)(out + r_hi * DD + col) = o; }
    }
}

// ---------------- launch ----------------
extern "C" void kernel_launch(void* const* d_in, const int* in_sizes, int n_in,
                              void* d_out, int out_size) {
    const float* x   = (const float*)d_in[0];
    const int*   src = (const int*)d_in[1];
    const int*   dst = (const int*)d_in[2];
    const float* W1  = (const float*)d_in[3];
    const float* b1  = (const float*)d_in[4];
    const float* W2  = (const float*)d_in[5];
    const float* b2  = (const float*)d_in[6];
    const float* pa  = (const float*)d_in[7];
    float* out = (float*)d_out;

    const int N = NN;
    const int E = EE;

    float *agg, *h, *wf1, *wf2;
    cudaGetSymbolAddress((void**)&agg, g_agg);
    cudaGetSymbolAddress((void**)&h, g_h);
    cudaGetSymbolAddress((void**)&wf1, g_wfrag1);
    cudaGetSymbolAddress((void**)&wf2, g_wfrag2);

    // Build CSR + normalization + W fragment tables
    k_init<<<(N + 255) / 256, 256>>>(N);
    k_deg<<<(E + 255) / 256, 256>>>(src, dst, E);
    k_scan1<<<NBLK, 1024>>>(N);
    k_scan2<<<1, 128>>>();
    k_scan3<<<(N + 255) / 256, 256>>>(N, E);
    k_scatter<<<(E + 255) / 256, 256>>>(src, dst, E);
    k_wfrag<<<32, 256>>>(W1, wf1);
    k_wfrag<<<32, 256>>>(W2, wf2);

    dim3 gt(32, 8);
    int gblocks = (N + 7) / 8;
    int mblocks = (N + 63) / 64;   // 1563

    // Layer 1: gather (with inv scaling) -> GEMM (epilogue pre-scales h by inv)
    k_gather<true><<<gblocks, gt>>>((const float4*)x, (float4*)agg, N);
    k_gemm_mma<true><<<mblocks, 256>>>(agg, wf1, b1, pa, h, N);
    // Layer 2: plain-sum gather -> GEMM (no output scaling)
    k_gather<false><<<gblocks, gt>>>((const float4*)h, (float4*)agg, N);
    k_gemm_mma<false><<<mblocks, 256>>>(agg, wf2, b2, pa, out, N);
}

// round 7
// speedup vs baseline: 1.4687x; 1.3609x over previous
#include <cuda_runtime.h>
#include <cuda_fp16.h>
#include <cstdint>

#define NN 100000
#define EE 1600000
#define DD 128
#define NBLK ((NN + 1023) / 1024)   // 98 scan blocks

// ---------------- static device scratch (no allocation allowed) ----------------
__device__ __half g_xh[NN * DD];        // x * inv[row], half
__device__ __half g_aggh[NN * DD];      // gather output, half
__device__ __half g_hh[NN * DD];        // layer-1 output * inv[row], half
__device__ uint2  g_wfrag1[8 * 16 * 32];  // W1 f16 B-fragment table (32KB)
__device__ uint2  g_wfrag2[8 * 16 * 32];  // W2 fragment table
__device__ int    g_outdeg[NN];
__device__ int    g_indeg[NN];
__device__ int    g_rowptr[NN + 1];
__device__ int    g_cursor[NN];
__device__ int    g_colidx[EE];
__device__ float  g_inv[NN];
__device__ int    g_bsum[NBLK];
__device__ int    g_boff[NBLK];

#define MMA_F16(c0, c1, c2, c3, a0, a1, a2, a3, b0, b1) \
    asm volatile("mma.sync.aligned.m16n8k16.row.col.f32.f16.f16.f32 " \
        "{%0,%1,%2,%3}, {%4,%5,%6,%7}, {%8,%9}, {%0,%1,%2,%3};" \
        : "+f"(c0), "+f"(c1), "+f"(c2), "+f"(c3) \
        : "r"(a0), "r"(a1), "r"(a2), "r"(a3), "r"(b0), "r"(b1))

__device__ __forceinline__ uint32_t h2bits(__half2 h) {
    return *(uint32_t*)&h;
}

// ---------------- build: degrees ----------------
__global__ void k_init(int N) {
    int i = blockIdx.x * blockDim.x + threadIdx.x;
    if (i < N) { g_outdeg[i] = 0; g_indeg[i] = 0; }
}

__global__ void k_deg(const int* __restrict__ src, const int* __restrict__ dst, int E) {
    int e = blockIdx.x * blockDim.x + threadIdx.x;
    if (e < E) {
        atomicAdd(&g_outdeg[src[e]], 1);
        atomicAdd(&g_indeg[dst[e]], 1);
    }
}

// ---------------- build: parallel exclusive scan ----------------
__global__ void k_scan1(int N) {
    __shared__ int s_w[32];
    int tid = threadIdx.x, lane = tid & 31, wid = tid >> 5;
    int i = blockIdx.x * 1024 + tid;
    int v = (i < N) ? g_indeg[i] : 0;
    int incl = v;
#pragma unroll
    for (int off = 1; off < 32; off <<= 1) {
        int t = __shfl_up_sync(0xffffffffu, incl, off);
        if (lane >= off) incl += t;
    }
    if (lane == 31) s_w[wid] = incl;
    __syncthreads();
    if (wid == 0) {
        int s = s_w[lane];
        int si = s;
#pragma unroll
        for (int off = 1; off < 32; off <<= 1) {
            int t = __shfl_up_sync(0xffffffffu, si, off);
            if (lane >= off) si += t;
        }
        s_w[lane] = si - s;
    }
    __syncthreads();
    int excl = incl - v + s_w[wid];
    if (i < N) g_rowptr[i] = excl;
    if (tid == 1023) g_bsum[blockIdx.x] = s_w[31] + incl;
}

__global__ void k_scan2() {
    __shared__ int s[NBLK];
    int tid = threadIdx.x;
    if (tid < NBLK) s[tid] = g_bsum[tid];
    __syncthreads();
    if (tid == 0) {
        int run = 0;
        for (int b = 0; b < NBLK; b++) { int t = s[b]; s[b] = run; run += t; }
    }
    __syncthreads();
    if (tid < NBLK) g_boff[tid] = s[tid];
}

// scan3 also computes inv
__global__ void k_scan3(int N, int E) {
    int i = blockIdx.x * blockDim.x + threadIdx.x;
    if (i < N) {
        int v = g_rowptr[i] + g_boff[i >> 10];
        g_rowptr[i] = v;
        g_cursor[i] = v;
        int d = g_outdeg[i];
        g_inv[i] = 1.0f / (float)(d > 1 ? d : 1);
    }
    if (i == 0) g_rowptr[N] = E;
}

__global__ void k_scatter(const int* __restrict__ src, const int* __restrict__ dst, int E) {
    int e = blockIdx.x * blockDim.x + threadIdx.x;
    if (e < E) {
        int p = atomicAdd(&g_cursor[dst[e]], 1);
        g_colidx[p] = src[e];
    }
}

// ---------------- x -> half, pre-scaled by inv[row] ----------------
__global__ void k_tohalf(const float4* __restrict__ x, uint2* __restrict__ xh, int N) {
    int i = blockIdx.x * blockDim.x + threadIdx.x;   // over N*32 float4 chunks
    if (i >= N * 32) return;
    float s = g_inv[i >> 5];
    float4 v = x[i];
    __half2 h01 = __floats2half2_rn(v.x * s, v.y * s);
    __half2 h23 = __floats2half2_rn(v.z * s, v.w * s);
    xh[i] = make_uint2(h2bits(h01), h2bits(h23));
}

// ---------------- pack W into f16 mma B-fragment table ----------------
// frag[(ks*16+nt)*32+lane] = { half2(W[k0+2r][col], W[k0+2r+1][col]),
//                              half2(W[k0+2r+8][col], W[k0+2r+9][col]) }
// k0 = ks*16, r = lane%4, col = nt*8 + lane/4.
__global__ void k_wfrag(const float* __restrict__ W, uint2* __restrict__ frag) {
    int idx = blockIdx.x * 256 + threadIdx.x;   // 0..4095
    if (idx >= 4096) return;
    int lane = idx & 31, nt = (idx >> 5) & 15, ks = idx >> 9;
    int k0 = ks * 16, col = nt * 8 + (lane >> 2), r = lane & 3;
    __half2 b0 = __floats2half2_rn(W[(k0 + 2 * r) * DD + col], W[(k0 + 2 * r + 1) * DD + col]);
    __half2 b1 = __floats2half2_rn(W[(k0 + 2 * r + 8) * DD + col], W[(k0 + 2 * r + 9) * DD + col]);
    frag[idx] = make_uint2(h2bits(b0), h2bits(b1));
}

// ---------------- SpMM gather (half features, plain sum, unroll x4) ----------------
__global__ void k_gather(const uint2* __restrict__ xin, uint2* __restrict__ out, int N) {
    int lane = threadIdx.x;
    int node = blockIdx.x * blockDim.y + threadIdx.y;
    if (node >= N) return;
    int beg = g_rowptr[node], end = g_rowptr[node + 1];
    float4 a0 = make_float4(0.f, 0.f, 0.f, 0.f);
    float4 a1 = make_float4(0.f, 0.f, 0.f, 0.f);
    int e = beg;
#pragma unroll 1
    for (; e + 4 <= end; e += 4) {
        int s0 = g_colidx[e + 0];
        int s1 = g_colidx[e + 1];
        int s2 = g_colidx[e + 2];
        int s3 = g_colidx[e + 3];
        uint2 v0 = xin[s0 * 32 + lane];
        uint2 v1 = xin[s1 * 32 + lane];
        uint2 v2 = xin[s2 * 32 + lane];
        uint2 v3 = xin[s3 * 32 + lane];
        float2 f;
        f = __half22float2(*(__half2*)&v0.x); a0.x += f.x; a0.y += f.y;
        f = __half22float2(*(__half2*)&v0.y); a0.z += f.x; a0.w += f.y;
        f = __half22float2(*(__half2*)&v1.x); a1.x += f.x; a1.y += f.y;
        f = __half22float2(*(__half2*)&v1.y); a1.z += f.x; a1.w += f.y;
        f = __half22float2(*(__half2*)&v2.x); a0.x += f.x; a0.y += f.y;
        f = __half22float2(*(__half2*)&v2.y); a0.z += f.x; a0.w += f.y;
        f = __half22float2(*(__half2*)&v3.x); a1.x += f.x; a1.y += f.y;
        f = __half22float2(*(__half2*)&v3.y); a1.z += f.x; a1.w += f.y;
    }
    for (; e < end; e++) {
        int s = g_colidx[e];
        uint2 v = xin[s * 32 + lane];
        float2 f;
        f = __half22float2(*(__half2*)&v.x); a0.x += f.x; a0.y += f.y;
        f = __half22float2(*(__half2*)&v.y); a0.z += f.x; a0.w += f.y;
    }
    a0.x += a1.x; a0.y += a1.y; a0.z += a1.z; a0.w += a1.w;
    __half2 h01 = __floats2half2_rn(a0.x, a0.y);
    __half2 h23 = __floats2half2_rn(a0.z, a0.w);
    out[node * 32 + lane] = make_uint2(h2bits(h01), h2bits(h23));
}

// ---------------- f16 mma GEMM + bias + PReLU ----------------
// CTA: 64 rows x 128 cols, 8 warps, warp tile 16x64, K=16 per mma (8 K-steps).
// HALF_OUT: write half (pre-scaled by g_inv[row]); else write fp32.
#define ASTRH 136    // half stride: conflict-free A-frag LDS
template <bool HALF_OUT>
__global__ __launch_bounds__(256)
void k_gemm_mma(const __half* __restrict__ A, const uint2* __restrict__ wfrag,
                const float* __restrict__ bias, const float* __restrict__ pa,
                void* __restrict__ outp, int N) {
    __shared__ __align__(16) __half As[64 * ASTRH];
    int tid = threadIdx.x;
    int lane = tid & 31, wid = tid >> 5;
    int rowgrp = wid & 3, colgrp = wid >> 2;
    int rbase = blockIdx.x * 64;

    // Fill A tile: 64 rows x 128 halves (8B chunks).
    const uint2* A2 = (const uint2*)A;
    for (int i = tid; i < 64 * 32; i += 256) {
        int r = i >> 5, c4 = i & 31;
        int row = rbase + r;
        if (row >= N) row = N - 1;   // clamp; extra rows never stored
        *(uint2*)&As[r * ASTRH + c4 * 4] = A2[row * 32 + c4];
    }
    __syncthreads();

    float c[8][4];
#pragma unroll
    for (int nt = 0; nt < 8; nt++)
#pragma unroll
        for (int j = 0; j < 4; j++) c[nt][j] = 0.f;

    const __half* Ab = As + (rowgrp * 16 + (lane >> 2)) * ASTRH + 2 * (lane & 3);

#pragma unroll
    for (int ks = 0; ks < 8; ks++) {
        int k0 = ks * 16;
        uint32_t a0 = *(const uint32_t*)&Ab[k0];
        uint32_t a1 = *(const uint32_t*)&Ab[8 * ASTRH + k0];
        uint32_t a2 = *(const uint32_t*)&Ab[k0 + 8];
        uint32_t a3 = *(const uint32_t*)&Ab[8 * ASTRH + k0 + 8];
        const uint2* wk = wfrag + (ks * 16 + colgrp * 8) * 32 + lane;
#pragma unroll
        for (int nt = 0; nt < 8; nt++) {
            uint2 bv = wk[nt * 32];
            MMA_F16(c[nt][0], c[nt][1], c[nt][2], c[nt][3],
                    a0, a1, a2, a3, bv.x, bv.y);
        }
    }

    float alpha = pa[0];
    int r_lo = rbase + rowgrp * 16 + (lane >> 2);
    int r_hi = r_lo + 8;
    float s_lo = 1.f, s_hi = 1.f;
    if (HALF_OUT) {
        if (r_lo < N) s_lo = g_inv[r_lo];
        if (r_hi < N) s_hi = g_inv[r_hi];
    }
#pragma unroll
    for (int nt = 0; nt < 8; nt++) {
        int col = colgrp * 64 + nt * 8 + (lane & 3) * 2;
        float2 bb = *(const float2*)(bias + col);
        float z0 = c[nt][0] + bb.x;
        float z1 = c[nt][1] + bb.y;
        float z2 = c[nt][2] + bb.x;
        float z3 = c[nt][3] + bb.y;
        z0 = (z0 >= 0.f) ? z0 : alpha * z0;
        z1 = (z1 >= 0.f) ? z1 : alpha * z1;
        z2 = (z2 >= 0.f) ? z2 : alpha * z2;
        z3 = (z3 >= 0.f) ? z3 : alpha * z3;
        if (HALF_OUT) {
            __half* outh = (__half*)outp;
            if (r_lo < N) {
                __half2 o = __floats2half2_rn(z0 * s_lo, z1 * s_lo);
                *(__half2*)(outh + r_lo * DD + col) = o;
            }
            if (r_hi < N) {
                __half2 o = __floats2half2_rn(z2 * s_hi, z3 * s_hi);
                *(__half2*)(outh + r_hi * DD + col) = o;
            }
        } else {
            float* outf = (float*)outp;
            if (r_lo < N) { float2 o = {z0, z1}; *(float2*)(outf + r_lo * DD + col) = o; }
            if (r_hi < N) { float2 o = {z2, z3}; *(float2*)(outf + r_hi * DD + col) = o; }
        }
    }
}

// ---------------- launch ----------------
extern "C" void kernel_launch(void* const* d_in, const int* in_sizes, int n_in,
                              void* d_out, int out_size) {
    const float* x   = (const float*)d_in[0];
    const int*   src = (const int*)d_in[1];
    const int*   dst = (const int*)d_in[2];
    const float* W1  = (const float*)d_in[3];
    const float* b1  = (const float*)d_in[4];
    const float* W2  = (const float*)d_in[5];
    const float* b2  = (const float*)d_in[6];
    const float* pa  = (const float*)d_in[7];
    float* out = (float*)d_out;

    const int N = NN;
    const int E = EE;

    __half *xh, *aggh, *hh;
    uint2 *wf1, *wf2;
    cudaGetSymbolAddress((void**)&xh, g_xh);
    cudaGetSymbolAddress((void**)&aggh, g_aggh);
    cudaGetSymbolAddress((void**)&hh, g_hh);
    cudaGetSymbolAddress((void**)&wf1, g_wfrag1);
    cudaGetSymbolAddress((void**)&wf2, g_wfrag2);

    // Build CSR + normalization
    k_init<<<(N + 255) / 256, 256>>>(N);
    k_deg<<<(E + 255) / 256, 256>>>(src, dst, E);
    k_scan1<<<NBLK, 1024>>>(N);
    k_scan2<<<1, 128>>>();
    k_scan3<<<(N + 255) / 256, 256>>>(N, E);
    k_scatter<<<(E + 255) / 256, 256>>>(src, dst, E);
    k_tohalf<<<(N * 32 + 255) / 256, 256>>>((const float4*)x, (uint2*)xh, N);
    k_wfrag<<<16, 256>>>(W1, wf1);
    k_wfrag<<<16, 256>>>(W2, wf2);

    dim3 gt(32, 8);
    int gblocks = (N + 7) / 8;
    int mblocks = (N + 63) / 64;   // 1563

    // Layer 1: plain-sum gather (xh pre-scaled) -> GEMM (writes hh = prelu(..)*inv, half)
    k_gather<<<gblocks, gt>>>((const uint2*)xh, (uint2*)aggh, N);
    k_gemm_mma<true><<<mblocks, 256>>>(aggh, wf1, b1, pa, hh, N);
    // Layer 2: plain-sum gather -> GEMM (writes fp32 d_out)
    k_gather<<<gblocks, gt>>>((const uint2*)hh, (uint2*)aggh, N);
    k_gemm_mma<false><<<mblocks, 256>>>(aggh, wf2, b2, pa, out, N);
}

// round 8
// speedup vs baseline: 1.5865x; 1.0802x over previous
#include <cuda_runtime.h>
#include <cuda_fp16.h>
#include <cstdint>

#define NN 100000
#define EE 1600000
#define DD 128
#define NBLK ((NN + 1023) / 1024)   // 98 scan blocks

// ---------------- static device scratch (no allocation allowed) ----------------
__device__ __half g_xh[NN * DD];        // x * inv[row], half
__device__ __half g_aggh[NN * DD];      // gather output, half
__device__ __half g_hh[NN * DD];        // layer-1 output * inv[row], half
__device__ uint2  g_wfrag1[8 * 16 * 32];  // W1 f16 B-fragment table (32KB)
__device__ uint2  g_wfrag2[8 * 16 * 32];  // W2 fragment table
__device__ int    g_outdeg[NN];
__device__ int    g_indeg[NN];
__device__ int    g_rowptr[NN + 1];
__device__ int    g_cursor[NN];
__device__ int    g_colidx[EE];
__device__ float  g_inv[NN];
__device__ int    g_bsum[NBLK];
__device__ int    g_boff[NBLK];

#define MMA_F16(c0, c1, c2, c3, a0, a1, a2, a3, b0, b1) \
    asm volatile("mma.sync.aligned.m16n8k16.row.col.f32.f16.f16.f32 " \
        "{%0,%1,%2,%3}, {%4,%5,%6,%7}, {%8,%9}, {%0,%1,%2,%3};" \
        : "+f"(c0), "+f"(c1), "+f"(c2), "+f"(c3) \
        : "r"(a0), "r"(a1), "r"(a2), "r"(a3), "r"(b0), "r"(b1))

__device__ __forceinline__ uint32_t h2bits(__half2 h) {
    return *(uint32_t*)&h;
}

// ---------------- build: degrees ----------------
__global__ void k_deg(const int* __restrict__ src, const int* __restrict__ dst, int E) {
    int e = blockIdx.x * blockDim.x + threadIdx.x;
    if (e < E) {
        atomicAdd(&g_outdeg[src[e]], 1);
        atomicAdd(&g_indeg[dst[e]], 1);
    }
}

// ---------------- build: parallel exclusive scan ----------------
__global__ void k_scan1(int N) {
    __shared__ int s_w[32];
    int tid = threadIdx.x, lane = tid & 31, wid = tid >> 5;
    int i = blockIdx.x * 1024 + tid;
    int v = (i < N) ? g_indeg[i] : 0;
    int incl = v;
#pragma unroll
    for (int off = 1; off < 32; off <<= 1) {
        int t = __shfl_up_sync(0xffffffffu, incl, off);
        if (lane >= off) incl += t;
    }
    if (lane == 31) s_w[wid] = incl;
    __syncthreads();
    if (wid == 0) {
        int s = s_w[lane];
        int si = s;
#pragma unroll
        for (int off = 1; off < 32; off <<= 1) {
            int t = __shfl_up_sync(0xffffffffu, si, off);
            if (lane >= off) si += t;
        }
        s_w[lane] = si - s;
    }
    __syncthreads();
    int excl = incl - v + s_w[wid];
    if (i < N) g_rowptr[i] = excl;
    if (tid == 1023) g_bsum[blockIdx.x] = s_w[31] + incl;
}

// parallel warp-shuffle scan over NBLK=98 block sums
__global__ void k_scan2() {
    __shared__ int s_w[4];
    int tid = threadIdx.x, lane = tid & 31, wid = tid >> 5;
    int v = (tid < NBLK) ? g_bsum[tid] : 0;
    int incl = v;
#pragma unroll
    for (int off = 1; off < 32; off <<= 1) {
        int t = __shfl_up_sync(0xffffffffu, incl, off);
        if (lane >= off) incl += t;
    }
    if (lane == 31) s_w[wid] = incl;
    __syncthreads();
    int woff = 0;
#pragma unroll
    for (int w = 0; w < 4; w++)
        if (w < wid) woff += s_w[w];
    if (tid < NBLK) g_boff[tid] = incl - v + woff;
}

// scan3 also computes inv
__global__ void k_scan3(int N, int E) {
    int i = blockIdx.x * blockDim.x + threadIdx.x;
    if (i < N) {
        int v = g_rowptr[i] + g_boff[i >> 10];
        g_rowptr[i] = v;
        g_cursor[i] = v;
        int d = g_outdeg[i];
        g_inv[i] = 1.0f / (float)(d > 1 ? d : 1);
    }
    if (i == 0) g_rowptr[N] = E;
}

// ---------------- merged scatter + x->half (both depend only on scan3) ----------------
#define SCAT_BLK ((EE + 255) / 256)        // 6250
#define TOH_BLK  ((NN * 32 + 255) / 256)   // 12500
__global__ void k_scatter_tohalf(const int* __restrict__ src, const int* __restrict__ dst,
                                 const float4* __restrict__ x, uint2* __restrict__ xh,
                                 int E, int N) {
    int b = blockIdx.x;
    if (b < SCAT_BLK) {
        int e = b * 256 + threadIdx.x;
        if (e < E) {
            int p = atomicAdd(&g_cursor[dst[e]], 1);
            g_colidx[p] = src[e];
        }
    } else {
        int i = (b - SCAT_BLK) * 256 + threadIdx.x;
        if (i < N * 32) {
            float s = g_inv[i >> 5];
            float4 v = x[i];
            __half2 h01 = __floats2half2_rn(v.x * s, v.y * s);
            __half2 h23 = __floats2half2_rn(v.z * s, v.w * s);
            xh[i] = make_uint2(h2bits(h01), h2bits(h23));
        }
    }
}

// ---------------- pack both W into f16 mma B-fragment tables (one launch) ----------------
__global__ void k_wfrag2x(const float* __restrict__ W1, uint2* __restrict__ f1,
                          const float* __restrict__ W2, uint2* __restrict__ f2) {
    int gb = blockIdx.x;
    const float* W = (gb < 16) ? W1 : W2;
    uint2* frag = (gb < 16) ? f1 : f2;
    int idx = (gb & 15) * 256 + threadIdx.x;   // 0..4095
    int lane = idx & 31, nt = (idx >> 5) & 15, ks = idx >> 9;
    int k0 = ks * 16, col = nt * 8 + (lane >> 2), r = lane & 3;
    __half2 b0 = __floats2half2_rn(W[(k0 + 2 * r) * DD + col], W[(k0 + 2 * r + 1) * DD + col]);
    __half2 b1 = __floats2half2_rn(W[(k0 + 2 * r + 8) * DD + col], W[(k0 + 2 * r + 9) * DD + col]);
    frag[idx] = make_uint2(h2bits(b0), h2bits(b1));
}

// ---------------- SpMM gather (half features, plain sum, unroll x4) ----------------
__global__ void k_gather(const uint2* __restrict__ xin, uint2* __restrict__ out, int N) {
    int lane = threadIdx.x;
    int node = blockIdx.x * blockDim.y + threadIdx.y;
    if (node >= N) return;
    int beg = g_rowptr[node], end = g_rowptr[node + 1];
    float4 a0 = make_float4(0.f, 0.f, 0.f, 0.f);
    float4 a1 = make_float4(0.f, 0.f, 0.f, 0.f);
    int e = beg;
#pragma unroll 1
    for (; e + 4 <= end; e += 4) {
        int s0 = g_colidx[e + 0];
        int s1 = g_colidx[e + 1];
        int s2 = g_colidx[e + 2];
        int s3 = g_colidx[e + 3];
        uint2 v0 = xin[s0 * 32 + lane];
        uint2 v1 = xin[s1 * 32 + lane];
        uint2 v2 = xin[s2 * 32 + lane];
        uint2 v3 = xin[s3 * 32 + lane];
        float2 f;
        f = __half22float2(*(__half2*)&v0.x); a0.x += f.x; a0.y += f.y;
        f = __half22float2(*(__half2*)&v0.y); a0.z += f.x; a0.w += f.y;
        f = __half22float2(*(__half2*)&v1.x); a1.x += f.x; a1.y += f.y;
        f = __half22float2(*(__half2*)&v1.y); a1.z += f.x; a1.w += f.y;
        f = __half22float2(*(__half2*)&v2.x); a0.x += f.x; a0.y += f.y;
        f = __half22float2(*(__half2*)&v2.y); a0.z += f.x; a0.w += f.y;
        f = __half22float2(*(__half2*)&v3.x); a1.x += f.x; a1.y += f.y;
        f = __half22float2(*(__half2*)&v3.y); a1.z += f.x; a1.w += f.y;
    }
    for (; e < end; e++) {
        int s = g_colidx[e];
        uint2 v = xin[s * 32 + lane];
        float2 f;
        f = __half22float2(*(__half2*)&v.x); a0.x += f.x; a0.y += f.y;
        f = __half22float2(*(__half2*)&v.y); a0.z += f.x; a0.w += f.y;
    }
    a0.x += a1.x; a0.y += a1.y; a0.z += a1.z; a0.w += a1.w;
    __half2 h01 = __floats2half2_rn(a0.x, a0.y);
    __half2 h23 = __floats2half2_rn(a0.z, a0.w);
    out[node * 32 + lane] = make_uint2(h2bits(h01), h2bits(h23));
}

// ---------------- f16 mma GEMM + bias + PReLU ----------------
// CTA: 128 rows x 128 cols, 8 warps, warp tile 32x64 (2 m-groups share each B frag).
#define ASTRH 136    // half stride: conflict-free A-frag LDS
template <bool HALF_OUT>
__global__ __launch_bounds__(256, 2)
void k_gemm_mma(const __half* __restrict__ A, const uint2* __restrict__ wfrag,
                const float* __restrict__ bias, const float* __restrict__ pa,
                void* __restrict__ outp, int N) {
    __shared__ __align__(16) __half As[128 * ASTRH];
    int tid = threadIdx.x;
    int lane = tid & 31, wid = tid >> 5;
    int rowgrp = wid & 3, colgrp = wid >> 2;
    int rbase = blockIdx.x * 128;

    // Fill A tile: 128 rows x 128 halves (8B chunks).
    const uint2* A2 = (const uint2*)A;
#pragma unroll 4
    for (int i = tid; i < 128 * 32; i += 256) {
        int r = i >> 5, c4 = i & 31;
        int row = rbase + r;
        if (row >= N) row = N - 1;   // clamp; extra rows never stored
        *(uint2*)&As[r * ASTRH + c4 * 4] = A2[row * 32 + c4];
    }
    __syncthreads();

    float c[2][8][4];
#pragma unroll
    for (int mg = 0; mg < 2; mg++)
#pragma unroll
        for (int nt = 0; nt < 8; nt++)
#pragma unroll
            for (int j = 0; j < 4; j++) c[mg][nt][j] = 0.f;

    const __half* Ab0 = As + (rowgrp * 32 + (lane >> 2)) * ASTRH + 2 * (lane & 3);
    const __half* Ab1 = Ab0 + 16 * ASTRH;

#pragma unroll
    for (int ks = 0; ks < 8; ks++) {
        int k0 = ks * 16;
        uint32_t a00 = *(const uint32_t*)&Ab0[k0];
        uint32_t a01 = *(const uint32_t*)&Ab0[8 * ASTRH + k0];
        uint32_t a02 = *(const uint32_t*)&Ab0[k0 + 8];
        uint32_t a03 = *(const uint32_t*)&Ab0[8 * ASTRH + k0 + 8];
        uint32_t a10 = *(const uint32_t*)&Ab1[k0];
        uint32_t a11 = *(const uint32_t*)&Ab1[8 * ASTRH + k0];
        uint32_t a12 = *(const uint32_t*)&Ab1[k0 + 8];
        uint32_t a13 = *(const uint32_t*)&Ab1[8 * ASTRH + k0 + 8];
        const uint2* wk = wfrag + (ks * 16 + colgrp * 8) * 32 + lane;
#pragma unroll
        for (int nt = 0; nt < 8; nt++) {
            uint2 bv = wk[nt * 32];
            MMA_F16(c[0][nt][0], c[0][nt][1], c[0][nt][2], c[0][nt][3],
                    a00, a01, a02, a03, bv.x, bv.y);
            MMA_F16(c[1][nt][0], c[1][nt][1], c[1][nt][2], c[1][nt][3],
                    a10, a11, a12, a13, bv.x, bv.y);
        }
    }

    float alpha = pa[0];
#pragma unroll
    for (int mg = 0; mg < 2; mg++) {
        int r_lo = rbase + rowgrp * 32 + mg * 16 + (lane >> 2);
        int r_hi = r_lo + 8;
        float s_lo = 1.f, s_hi = 1.f;
        if (HALF_OUT) {
            if (r_lo < N) s_lo = g_inv[r_lo];
            if (r_hi < N) s_hi = g_inv[r_hi];
        }
#pragma unroll
        for (int nt = 0; nt < 8; nt++) {
            int col = colgrp * 64 + nt * 8 + (lane & 3) * 2;
            float2 bb = *(const float2*)(bias + col);
            float z0 = c[mg][nt][0] + bb.x;
            float z1 = c[mg][nt][1] + bb.y;
            float z2 = c[mg][nt][2] + bb.x;
            float z3 = c[mg][nt][3] + bb.y;
            z0 = (z0 >= 0.f) ? z0 : alpha * z0;
            z1 = (z1 >= 0.f) ? z1 : alpha * z1;
            z2 = (z2 >= 0.f) ? z2 : alpha * z2;
            z3 = (z3 >= 0.f) ? z3 : alpha * z3;
            if (HALF_OUT) {
                __half* outh = (__half*)outp;
                if (r_lo < N) {
                    __half2 o = __floats2half2_rn(z0 * s_lo, z1 * s_lo);
                    *(__half2*)(outh + r_lo * DD + col) = o;
                }
                if (r_hi < N) {
                    __half2 o = __floats2half2_rn(z2 * s_hi, z3 * s_hi);
                    *(__half2*)(outh + r_hi * DD + col) = o;
                }
            } else {
                float* outf = (float*)outp;
                if (r_lo < N) { float2 o = {z0, z1}; *(float2*)(outf + r_lo * DD + col) = o; }
                if (r_hi < N) { float2 o = {z2, z3}; *(float2*)(outf + r_hi * DD + col) = o; }
            }
        }
    }
}

// ---------------- launch ----------------
extern "C" void kernel_launch(void* const* d_in, const int* in_sizes, int n_in,
                              void* d_out, int out_size) {
    const float* x   = (const float*)d_in[0];
    const int*   src = (const int*)d_in[1];
    const int*   dst = (const int*)d_in[2];
    const float* W1  = (const float*)d_in[3];
    const float* b1  = (const float*)d_in[4];
    const float* W2  = (const float*)d_in[5];
    const float* b2  = (const float*)d_in[6];
    const float* pa  = (const float*)d_in[7];
    float* out = (float*)d_out;

    const int N = NN;
    const int E = EE;

    __half *xh, *aggh, *hh;
    uint2 *wf1, *wf2;
    int *outdeg, *indeg;
    cudaGetSymbolAddress((void**)&xh, g_xh);
    cudaGetSymbolAddress((void**)&aggh, g_aggh);
    cudaGetSymbolAddress((void**)&hh, g_hh);
    cudaGetSymbolAddress((void**)&wf1, g_wfrag1);
    cudaGetSymbolAddress((void**)&wf2, g_wfrag2);
    cudaGetSymbolAddress((void**)&outdeg, g_outdeg);
    cudaGetSymbolAddress((void**)&indeg, g_indeg);

    // Build CSR + normalization
    cudaMemsetAsync(outdeg, 0, N * sizeof(int));
    cudaMemsetAsync(indeg, 0, N * sizeof(int));
    k_deg<<<(E + 255) / 256, 256>>>(src, dst, E);
    k_scan1<<<NBLK, 1024>>>(N);
    k_scan2<<<1, 128>>>();
    k_scan3<<<(N + 255) / 256, 256>>>(N, E);
    k_scatter_tohalf<<<SCAT_BLK + TOH_BLK, 256>>>(src, dst, (const float4*)x, (uint2*)xh, E, N);
    k_wfrag2x<<<32, 256>>>(W1, wf1, W2, wf2);

    dim3 gt(32, 8);
    int gblocks = (N + 7) / 8;
    int mblocks = (N + 127) / 128;   // 782

    // Layer 1: plain-sum gather (xh pre-scaled) -> GEMM (writes hh = prelu(..)*inv, half)
    k_gather<<<gblocks, gt>>>((const uint2*)xh, (uint2*)aggh, N);
    k_gemm_mma<true><<<mblocks, 256>>>(aggh, wf1, b1, pa, hh, N);
    // Layer 2: plain-sum gather -> GEMM (writes fp32 d_out)
    k_gather<<<gblocks, gt>>>((const uint2*)hh, (uint2*)aggh, N);
    k_gemm_mma<false><<<mblocks, 256>>>(aggh, wf2, b2, pa, out, N);
}